// round 1
// baseline (speedup 1.0000x reference)
#include <cuda_runtime.h>
#include <cuda_bf16.h>
#include <cstdint>

// Problem constants
#define T_TOK 2048
#define HDIM  1024
#define FDIM  1024
#define NEXP  8
#define TOPK  2
#define NPAIR (T_TOK * TOPK)

// Tiling
#define BM 128
#define BN 64
#define BK 16
#define SSTR 20              // shared row stride (16 + 4 pad -> conflict-free frag loads)
#define MAX_TILES 40         // sum ceil(cnt_e/128) <= (4096 + 8*127)/128 = 39
#define PAD_ROWS (MAX_TILES * BM)

// Scratch (static device globals; no allocations allowed)
__device__ int   d_sorted[PAD_ROWS];        // pair id (t*2+k) or -1 padding
__device__ int   d_tile_expert[MAX_TILES];
__device__ int   d_ntiles;
__device__ float d_act[(size_t)PAD_ROWS * FDIM];   // 20 MB
__device__ float d_y2[(size_t)NPAIR * HDIM];       // 16 MB

// ---------------------------------------------------------------------------
// Routing: group pairs by expert into BM-aligned segments.
// ---------------------------------------------------------------------------
__global__ void route_kernel(const int* __restrict__ ids) {
    __shared__ int s_cnt[NEXP], s_start[NEXP], s_cur[NEXP];
    int tid = threadIdx.x;
    if (tid < NEXP) s_cnt[tid] = 0;
    __syncthreads();
    for (int p = tid; p < NPAIR; p += blockDim.x)
        atomicAdd(&s_cnt[ids[p]], 1);
    __syncthreads();
    if (tid == 0) {
        int acc = 0, nt = 0;
        for (int e = 0; e < NEXP; e++) {
            s_start[e] = acc;
            int te = (s_cnt[e] + BM - 1) / BM;
            for (int i = 0; i < te; i++) d_tile_expert[nt + i] = e;
            nt += te;
            acc += te * BM;
        }
        d_ntiles = nt;
    }
    __syncthreads();
    for (int i = tid; i < PAD_ROWS; i += blockDim.x) d_sorted[i] = -1;
    if (tid < NEXP) s_cur[tid] = s_start[tid];
    __syncthreads();
    for (int p = tid; p < NPAIR; p += blockDim.x) {
        int e = ids[p];
        int pos = atomicAdd(&s_cur[e], 1);
        d_sorted[pos] = p;
    }
}

// ---------------------------------------------------------------------------
// TF32 mma helpers
// ---------------------------------------------------------------------------
__device__ __forceinline__ uint32_t f2tf(float x) {
    uint32_t r;
    asm("cvt.rna.tf32.f32 %0, %1;" : "=r"(r) : "f"(x));
    return r;
}

__device__ __forceinline__ void mma8(float* d, const uint32_t* a, const uint32_t* b) {
    asm volatile(
        "mma.sync.aligned.m16n8k8.row.col.f32.tf32.tf32.f32 "
        "{%0,%1,%2,%3}, {%4,%5,%6,%7}, {%8,%9}, {%0,%1,%2,%3};"
        : "+f"(d[0]), "+f"(d[1]), "+f"(d[2]), "+f"(d[3])
        : "r"(a[0]), "r"(a[1]), "r"(a[2]), "r"(a[3]), "r"(b[0]), "r"(b[1]));
}

// ---------------------------------------------------------------------------
// GEMM1: act[m,f] = silu(x @ Wg^T) * (x @ Wu^T)  per expert tile
// A = gathered hidden rows (BMxBK), B = gate/up weight rows (BNxBK, k-contig)
// ---------------------------------------------------------------------------
__global__ __launch_bounds__(256) void gemm1_kernel(
    const float* __restrict__ hs, const float* __restrict__ gw) {
    int tile = blockIdx.x;
    if (tile >= d_ntiles) return;
    int e  = d_tile_expert[tile];
    int f0 = blockIdx.y * BN;

    __shared__ __align__(16) uint32_t As[BM * SSTR];
    __shared__ __align__(16) uint32_t Bg[BN * SSTR];
    __shared__ __align__(16) uint32_t Bu[BN * SSTR];
    __shared__ int s_tok[BM];

    int tid = threadIdx.x;
    if (tid < BM) {
        int sp = d_sorted[tile * BM + tid];
        s_tok[tid] = (sp >= 0) ? (sp >> 1) : -1;
    }
    __syncthreads();

    int lane = tid & 31, warp = tid >> 5;
    int wm = warp & 3, wn = warp >> 2;
    int m_base = wm * 32, n_base = wn * 32;

    float accG[2][4][4], accU[2][4][4];
    #pragma unroll
    for (int mt = 0; mt < 2; mt++)
        #pragma unroll
        for (int nt = 0; nt < 4; nt++)
            #pragma unroll
            for (int i = 0; i < 4; i++) { accG[mt][nt][i] = 0.f; accU[mt][nt][i] = 0.f; }

    const float* gwe = gw + (size_t)e * (2 * FDIM) * HDIM;

    for (int kb = 0; kb < HDIM / BK; kb++) {
        int k0 = kb * BK;
        // A tile: 128x16 floats = 512 float4, 2 per thread
        #pragma unroll
        for (int i = 0; i < 2; i++) {
            int s = tid + i * 256;
            int row = s >> 2, c4 = s & 3;
            int tok = s_tok[row];
            float4 v = make_float4(0.f, 0.f, 0.f, 0.f);
            if (tok >= 0)
                v = *(const float4*)(hs + (size_t)tok * HDIM + k0 + c4 * 4);
            uint4 u;
            u.x = f2tf(v.x); u.y = f2tf(v.y); u.z = f2tf(v.z); u.w = f2tf(v.w);
            *(uint4*)&As[row * SSTR + c4 * 4] = u;
        }
        // B tiles: 64x16 each, 1 float4 per thread per matrix
        {
            int row = tid >> 2, c4 = tid & 3;
            float4 v = *(const float4*)(gwe + (size_t)(f0 + row) * HDIM + k0 + c4 * 4);
            uint4 u;
            u.x = f2tf(v.x); u.y = f2tf(v.y); u.z = f2tf(v.z); u.w = f2tf(v.w);
            *(uint4*)&Bg[row * SSTR + c4 * 4] = u;
            v = *(const float4*)(gwe + (size_t)(FDIM + f0 + row) * HDIM + k0 + c4 * 4);
            u.x = f2tf(v.x); u.y = f2tf(v.y); u.z = f2tf(v.z); u.w = f2tf(v.w);
            *(uint4*)&Bu[row * SSTR + c4 * 4] = u;
        }
        __syncthreads();
        #pragma unroll
        for (int ks = 0; ks < 2; ks++) {
            int kk = ks * 8;
            uint32_t af[2][4], bgf[4][2], buf_[4][2];
            #pragma unroll
            for (int mt = 0; mt < 2; mt++) {
                int r = m_base + mt * 16 + (lane >> 2);
                int c = kk + (lane & 3);
                af[mt][0] = As[r * SSTR + c];
                af[mt][1] = As[(r + 8) * SSTR + c];
                af[mt][2] = As[r * SSTR + c + 4];
                af[mt][3] = As[(r + 8) * SSTR + c + 4];
            }
            #pragma unroll
            for (int nt = 0; nt < 4; nt++) {
                int n = n_base + nt * 8 + (lane >> 2);
                int c = kk + (lane & 3);
                bgf[nt][0]  = Bg[n * SSTR + c];
                bgf[nt][1]  = Bg[n * SSTR + c + 4];
                buf_[nt][0] = Bu[n * SSTR + c];
                buf_[nt][1] = Bu[n * SSTR + c + 4];
            }
            #pragma unroll
            for (int mt = 0; mt < 2; mt++)
                #pragma unroll
                for (int nt = 0; nt < 4; nt++) {
                    mma8(accG[mt][nt], af[mt], bgf[nt]);
                    mma8(accU[mt][nt], af[mt], buf_[nt]);
                }
        }
        __syncthreads();
    }

    // Epilogue: silu(g)*u -> act scratch (padded rows store zeros; harmless)
    #pragma unroll
    for (int mt = 0; mt < 2; mt++)
        #pragma unroll
        for (int nt = 0; nt < 4; nt++)
            #pragma unroll
            for (int half = 0; half < 2; half++) {
                int r = m_base + mt * 16 + (lane >> 2) + half * 8;
                int c = n_base + nt * 8 + (lane & 3) * 2;
                float g0 = accG[mt][nt][half * 2 + 0];
                float g1 = accG[mt][nt][half * 2 + 1];
                float u0 = accU[mt][nt][half * 2 + 0];
                float u1 = accU[mt][nt][half * 2 + 1];
                float a0 = g0 / (1.f + __expf(-g0)) * u0;
                float a1 = g1 / (1.f + __expf(-g1)) * u1;
                *(float2*)&d_act[(size_t)(tile * BM + r) * FDIM + f0 + c] =
                    make_float2(a0, a1);
            }
}

// ---------------------------------------------------------------------------
// GEMM2: y2[pair,h] = w[pair] * (act[m,:] @ Wd[e,h,:])
// ---------------------------------------------------------------------------
__global__ __launch_bounds__(256) void gemm2_kernel(
    const float* __restrict__ dw, const float* __restrict__ tw) {
    int tile = blockIdx.x;
    if (tile >= d_ntiles) return;
    int e  = d_tile_expert[tile];
    int h0 = blockIdx.y * BN;

    __shared__ __align__(16) uint32_t As[BM * SSTR];
    __shared__ __align__(16) uint32_t Bs[BN * SSTR];

    int tid = threadIdx.x;
    int lane = tid & 31, warp = tid >> 5;
    int wm = warp & 3, wn = warp >> 2;
    int m_base = wm * 32, n_base = wn * 32;

    float acc[2][4][4];
    #pragma unroll
    for (int mt = 0; mt < 2; mt++)
        #pragma unroll
        for (int nt = 0; nt < 4; nt++)
            #pragma unroll
            for (int i = 0; i < 4; i++) acc[mt][nt][i] = 0.f;

    const float* dwe = dw + (size_t)e * HDIM * FDIM;

    for (int kb = 0; kb < FDIM / BK; kb++) {
        int k0 = kb * BK;
        #pragma unroll
        for (int i = 0; i < 2; i++) {
            int s = tid + i * 256;
            int row = s >> 2, c4 = s & 3;
            float4 v = *(const float4*)(d_act + (size_t)(tile * BM + row) * FDIM + k0 + c4 * 4);
            uint4 u;
            u.x = f2tf(v.x); u.y = f2tf(v.y); u.z = f2tf(v.z); u.w = f2tf(v.w);
            *(uint4*)&As[row * SSTR + c4 * 4] = u;
        }
        {
            int row = tid >> 2, c4 = tid & 3;
            float4 v = *(const float4*)(dwe + (size_t)(h0 + row) * FDIM + k0 + c4 * 4);
            uint4 u;
            u.x = f2tf(v.x); u.y = f2tf(v.y); u.z = f2tf(v.z); u.w = f2tf(v.w);
            *(uint4*)&Bs[row * SSTR + c4 * 4] = u;
        }
        __syncthreads();
        #pragma unroll
        for (int ks = 0; ks < 2; ks++) {
            int kk = ks * 8;
            uint32_t af[2][4], bf[4][2];
            #pragma unroll
            for (int mt = 0; mt < 2; mt++) {
                int r = m_base + mt * 16 + (lane >> 2);
                int c = kk + (lane & 3);
                af[mt][0] = As[r * SSTR + c];
                af[mt][1] = As[(r + 8) * SSTR + c];
                af[mt][2] = As[r * SSTR + c + 4];
                af[mt][3] = As[(r + 8) * SSTR + c + 4];
            }
            #pragma unroll
            for (int nt = 0; nt < 4; nt++) {
                int n = n_base + nt * 8 + (lane >> 2);
                int c = kk + (lane & 3);
                bf[nt][0] = Bs[n * SSTR + c];
                bf[nt][1] = Bs[n * SSTR + c + 4];
            }
            #pragma unroll
            for (int mt = 0; mt < 2; mt++)
                #pragma unroll
                for (int nt = 0; nt < 4; nt++)
                    mma8(acc[mt][nt], af[mt], bf[nt]);
        }
        __syncthreads();
    }

    // Epilogue: scale by topk weight, store into per-pair y2 (no atomics)
    #pragma unroll
    for (int mt = 0; mt < 2; mt++)
        #pragma unroll
        for (int half = 0; half < 2; half++) {
            int r = m_base + mt * 16 + (lane >> 2) + half * 8;
            int sp = d_sorted[tile * BM + r];
            if (sp < 0) continue;
            float w = tw[sp];
            #pragma unroll
            for (int nt = 0; nt < 4; nt++) {
                int c = n_base + nt * 8 + (lane & 3) * 2;
                float v0 = w * acc[mt][nt][half * 2 + 0];
                float v1 = w * acc[mt][nt][half * 2 + 1];
                *(float2*)&d_y2[(size_t)sp * HDIM + h0 + c] = make_float2(v0, v1);
            }
        }
}

// ---------------------------------------------------------------------------
// Reduce: out[t,:] = y2[2t,:] + y2[2t+1,:]
// ---------------------------------------------------------------------------
__global__ void reduce_kernel(float* __restrict__ out) {
    int i = blockIdx.x * blockDim.x + threadIdx.x;   // over T*H/4 float4s
    int t = i >> 8;          // H/4 = 256 float4 per row
    int c4 = i & 255;
    const float4* y = (const float4*)d_y2;
    float4 a = y[(size_t)(t * 2) * 256 + c4];
    float4 b = y[(size_t)(t * 2 + 1) * 256 + c4];
    ((float4*)out)[i] = make_float4(a.x + b.x, a.y + b.y, a.z + b.z, a.w + b.w);
}

// ---------------------------------------------------------------------------
extern "C" void kernel_launch(void* const* d_in, const int* in_sizes, int n_in,
                              void* d_out, int out_size) {
    const float* hs  = (const float*)d_in[0];
    const float* tw  = (const float*)d_in[1];
    const int*   ids = (const int*)d_in[2];
    const float* gw  = (const float*)d_in[3];
    const float* dw  = (const float*)d_in[4];

    route_kernel<<<1, 256>>>(ids);
    gemm1_kernel<<<dim3(MAX_TILES, FDIM / BN), 256>>>(hs, gw);
    gemm2_kernel<<<dim3(MAX_TILES, HDIM / BN), 256>>>(dw, tw);
    reduce_kernel<<<(T_TOK * HDIM / 4) / 256, 256>>>((float*)d_out);
}

// round 3
// speedup vs baseline: 1.1760x; 1.1760x over previous
#include <cuda_runtime.h>
#include <cuda_bf16.h>
#include <cstdint>

// Problem constants
#define T_TOK 2048
#define HDIM  1024
#define FDIM  1024
#define NEXP  8
#define TOPK  2
#define NPAIR (T_TOK * TOPK)

// Tiling
#define BM 128
#define BN 64
#define BK 32
#define NCH (HDIM / BK)          // 32 chunks (HDIM == FDIM)
#define SSTR 36                  // smem row stride in floats (32 + 4 pad)
#define STAGES 3
#define MAX_TILES 40
#define PAD_ROWS (MAX_TILES * BM)

// Per-stage smem (floats)
#define A_FLOATS  (BM * SSTR)            // 4608
#define B_FLOATS  (BN * SSTR)            // 2304
#define STG1_FLOATS (A_FLOATS + 2 * B_FLOATS)   // gemm1: A + Bg + Bu = 9216
#define STG2_FLOATS (A_FLOATS + B_FLOATS)       // gemm2: A + B      = 6912
#define SMEM1_BYTES (STAGES * STG1_FLOATS * 4)  // 110592
#define SMEM2_BYTES (STAGES * STG2_FLOATS * 4)  // 82944

// Scratch (static device globals; no allocations allowed)
__device__ int   d_sorted[PAD_ROWS];
__device__ int   d_tile_expert[MAX_TILES];
__device__ int   d_ntiles;
__device__ float d_act[(size_t)PAD_ROWS * FDIM];   // 20 MB
__device__ float d_y2[(size_t)NPAIR * HDIM];       // 16 MB

// ---------------------------------------------------------------------------
// Helpers
// ---------------------------------------------------------------------------
__device__ __forceinline__ uint32_t smem_u32(const void* p) {
    uint32_t a;
    asm("{ .reg .u64 t; cvta.to.shared.u64 t, %1; cvt.u32.u64 %0, t; }" : "=r"(a) : "l"(p));
    return a;
}
__device__ __forceinline__ void cpa16(uint32_t dst, const void* src) {
    asm volatile("cp.async.cg.shared.global [%0], [%1], 16;" :: "r"(dst), "l"(src));
}
__device__ __forceinline__ void cpa16z(uint32_t dst, const void* src, int sz) {
    asm volatile("cp.async.cg.shared.global [%0], [%1], 16, %2;"
                 :: "r"(dst), "l"(src), "r"(sz));
}
#define CPA_COMMIT() asm volatile("cp.async.commit_group;" ::: "memory")
#define CPA_WAIT1()  asm volatile("cp.async.wait_group 1;" ::: "memory")

__device__ __forceinline__ uint32_t f2tf(float x) {
    uint32_t r;
    asm("cvt.rna.tf32.f32 %0, %1;" : "=r"(r) : "f"(x));
    return r;
}
__device__ __forceinline__ void mma8(float* d, const uint32_t* a, const uint32_t* b) {
    asm volatile(
        "mma.sync.aligned.m16n8k8.row.col.f32.tf32.tf32.f32 "
        "{%0,%1,%2,%3}, {%4,%5,%6,%7}, {%8,%9}, {%0,%1,%2,%3};"
        : "+f"(d[0]), "+f"(d[1]), "+f"(d[2]), "+f"(d[3])
        : "r"(a[0]), "r"(a[1]), "r"(a[2]), "r"(a[3]), "r"(b[0]), "r"(b[1]));
}

// ---------------------------------------------------------------------------
// Routing: group pairs by expert into BM-aligned segments
// ---------------------------------------------------------------------------
__global__ void route_kernel(const int* __restrict__ ids) {
    __shared__ int s_cnt[NEXP], s_start[NEXP], s_cur[NEXP];
    int tid = threadIdx.x;
    if (tid < NEXP) s_cnt[tid] = 0;
    __syncthreads();
    for (int p = tid; p < NPAIR; p += blockDim.x) atomicAdd(&s_cnt[ids[p]], 1);
    __syncthreads();
    if (tid == 0) {
        int acc = 0, nt = 0;
        for (int e = 0; e < NEXP; e++) {
            s_start[e] = acc;
            int te = (s_cnt[e] + BM - 1) / BM;
            for (int i = 0; i < te; i++) d_tile_expert[nt + i] = e;
            nt += te;
            acc += te * BM;
        }
        d_ntiles = nt;
    }
    __syncthreads();
    for (int i = tid; i < PAD_ROWS; i += blockDim.x) d_sorted[i] = -1;
    if (tid < NEXP) s_cur[tid] = s_start[tid];
    __syncthreads();
    for (int p = tid; p < NPAIR; p += blockDim.x) {
        int pos = atomicAdd(&s_cur[ids[p]], 1);
        d_sorted[pos] = p;
    }
}

// ---------------------------------------------------------------------------
// GEMM1: act = silu(x @ Wg^T) * (x @ Wu^T). Grid (MAX_TILES, 16), 256 thr.
// 3-stage cp.async pipeline, BK=32.
// ---------------------------------------------------------------------------
__global__ __launch_bounds__(256, 1)
void gemm1_kernel(const float* __restrict__ hs, const float* __restrict__ gw) {
    int tile = blockIdx.x;
    if (tile >= d_ntiles) return;
    int e  = d_tile_expert[tile];
    int f0 = blockIdx.y * BN;

    extern __shared__ __align__(16) float smem[];
    __shared__ int s_tok[BM];

    int tid = threadIdx.x, lane = tid & 31, warp = tid >> 5;
    if (tid < BM) {
        int sp = d_sorted[tile * BM + tid];
        s_tok[tid] = (sp >= 0) ? (sp >> 1) : -1;
    }
    __syncthreads();

    const float* gwe = gw + (size_t)e * (2 * FDIM) * HDIM;
    uint32_t sbase = smem_u32(smem);

    // Load issue: A = 1024 float4 (4/thread), Bg = 512 (2/thread), Bu = 512
    int a_row[4], a_c4[4];
    const float* a_src[4];
    #pragma unroll
    for (int i = 0; i < 4; i++) {
        int idx = tid + i * 256;
        a_row[i] = idx >> 3; a_c4[i] = idx & 7;
        int tok = s_tok[a_row[i]];
        a_src[i] = (tok >= 0) ? (hs + (size_t)tok * HDIM + a_c4[i] * 4) : hs;
    }
    int a_sz[4];
    #pragma unroll
    for (int i = 0; i < 4; i++) a_sz[i] = (s_tok[a_row[i]] >= 0) ? 16 : 0;

    auto issue = [&](int c) {
        int stg = (c % STAGES) * STG1_FLOATS;
        int k0 = c * BK;
        uint32_t abase = sbase + stg * 4;
        #pragma unroll
        for (int i = 0; i < 4; i++)
            cpa16z(abase + (a_row[i] * SSTR + a_c4[i] * 4) * 4,
                   a_src[i] + k0 * (a_sz[i] ? 1 : 0), a_sz[i]);
        uint32_t bgbase = abase + A_FLOATS * 4;
        uint32_t bubase = bgbase + B_FLOATS * 4;
        #pragma unroll
        for (int i = 0; i < 2; i++) {
            int idx = tid + i * 256;
            int row = idx >> 3, c4 = idx & 7;
            cpa16(bgbase + (row * SSTR + c4 * 4) * 4,
                  gwe + (size_t)(f0 + row) * HDIM + k0 + c4 * 4);
            cpa16(bubase + (row * SSTR + c4 * 4) * 4,
                  gwe + (size_t)(FDIM + f0 + row) * HDIM + k0 + c4 * 4);
        }
    };

    int wm = warp & 3, wn = warp >> 2;
    int m_base = wm * 32, n_base = wn * 32;

    float accG[2][4][4], accU[2][4][4];
    #pragma unroll
    for (int mt = 0; mt < 2; mt++)
        #pragma unroll
        for (int nt = 0; nt < 4; nt++)
            #pragma unroll
            for (int i = 0; i < 4; i++) { accG[mt][nt][i] = 0.f; accU[mt][nt][i] = 0.f; }

    issue(0); CPA_COMMIT();
    issue(1); CPA_COMMIT();

    for (int c = 0; c < NCH; c++) {
        CPA_WAIT1();
        __syncthreads();
        if (c + 2 < NCH) issue(c + 2);
        CPA_COMMIT();

        const float* As = smem + (c % STAGES) * STG1_FLOATS;
        const float* Bg = As + A_FLOATS;
        const float* Bu = Bg + B_FLOATS;

        #pragma unroll
        for (int ks = 0; ks < 4; ks++) {
            int kk = ks * 8;
            uint32_t af[2][4], bgf[4][2], buf_[4][2];
            #pragma unroll
            for (int mt = 0; mt < 2; mt++) {
                int r = m_base + mt * 16 + (lane >> 2);
                int cc = kk + (lane & 3);
                af[mt][0] = f2tf(As[r * SSTR + cc]);
                af[mt][1] = f2tf(As[(r + 8) * SSTR + cc]);
                af[mt][2] = f2tf(As[r * SSTR + cc + 4]);
                af[mt][3] = f2tf(As[(r + 8) * SSTR + cc + 4]);
            }
            #pragma unroll
            for (int nt = 0; nt < 4; nt++) {
                int n = n_base + nt * 8 + (lane >> 2);
                int cc = kk + (lane & 3);
                bgf[nt][0]  = f2tf(Bg[n * SSTR + cc]);
                bgf[nt][1]  = f2tf(Bg[n * SSTR + cc + 4]);
                buf_[nt][0] = f2tf(Bu[n * SSTR + cc]);
                buf_[nt][1] = f2tf(Bu[n * SSTR + cc + 4]);
            }
            #pragma unroll
            for (int mt = 0; mt < 2; mt++)
                #pragma unroll
                for (int nt = 0; nt < 4; nt++) {
                    mma8(accG[mt][nt], af[mt], bgf[nt]);
                    mma8(accU[mt][nt], af[mt], buf_[nt]);
                }
        }
    }

    // Epilogue: silu(g)*u -> act scratch
    #pragma unroll
    for (int mt = 0; mt < 2; mt++)
        #pragma unroll
        for (int nt = 0; nt < 4; nt++)
            #pragma unroll
            for (int half = 0; half < 2; half++) {
                int r = m_base + mt * 16 + (lane >> 2) + half * 8;
                int cc = n_base + nt * 8 + (lane & 3) * 2;
                float g0 = accG[mt][nt][half * 2 + 0];
                float g1 = accG[mt][nt][half * 2 + 1];
                float u0 = accU[mt][nt][half * 2 + 0];
                float u1 = accU[mt][nt][half * 2 + 1];
                float a0 = g0 / (1.f + __expf(-g0)) * u0;
                float a1 = g1 / (1.f + __expf(-g1)) * u1;
                *(float2*)&d_act[(size_t)(tile * BM + r) * FDIM + f0 + cc] =
                    make_float2(a0, a1);
            }
}

// ---------------------------------------------------------------------------
// GEMM2: y2[pair] = tw[pair] * (act @ Wd[e]^T). Grid (MAX_TILES, 16), 256 thr.
// ---------------------------------------------------------------------------
__global__ __launch_bounds__(256, 1)
void gemm2_kernel(const float* __restrict__ dw, const float* __restrict__ tw) {
    int tile = blockIdx.x;
    if (tile >= d_ntiles) return;
    int e  = d_tile_expert[tile];
    int h0 = blockIdx.y * BN;

    extern __shared__ __align__(16) float smem[];

    int tid = threadIdx.x, lane = tid & 31, warp = tid >> 5;
    const float* dwe = dw + (size_t)e * HDIM * FDIM;
    const float* arow = d_act + (size_t)tile * BM * FDIM;
    uint32_t sbase = smem_u32(smem);

    auto issue = [&](int c) {
        int stg = (c % STAGES) * STG2_FLOATS;
        int k0 = c * BK;
        uint32_t abase = sbase + stg * 4;
        #pragma unroll
        for (int i = 0; i < 4; i++) {
            int idx = tid + i * 256;
            int row = idx >> 3, c4 = idx & 7;
            cpa16(abase + (row * SSTR + c4 * 4) * 4,
                  arow + (size_t)row * FDIM + k0 + c4 * 4);
        }
        uint32_t bbase = abase + A_FLOATS * 4;
        #pragma unroll
        for (int i = 0; i < 2; i++) {
            int idx = tid + i * 256;
            int row = idx >> 3, c4 = idx & 7;
            cpa16(bbase + (row * SSTR + c4 * 4) * 4,
                  dwe + (size_t)(h0 + row) * FDIM + k0 + c4 * 4);
        }
    };

    int wm = warp & 3, wn = warp >> 2;
    int m_base = wm * 32, n_base = wn * 32;

    float acc[2][4][4];
    #pragma unroll
    for (int mt = 0; mt < 2; mt++)
        #pragma unroll
        for (int nt = 0; nt < 4; nt++)
            #pragma unroll
            for (int i = 0; i < 4; i++) acc[mt][nt][i] = 0.f;

    issue(0); CPA_COMMIT();
    issue(1); CPA_COMMIT();

    for (int c = 0; c < NCH; c++) {
        CPA_WAIT1();
        __syncthreads();
        if (c + 2 < NCH) issue(c + 2);
        CPA_COMMIT();

        const float* As = smem + (c % STAGES) * STG2_FLOATS;
        const float* Bs = As + A_FLOATS;

        #pragma unroll
        for (int ks = 0; ks < 4; ks++) {
            int kk = ks * 8;
            uint32_t af[2][4], bf[4][2];
            #pragma unroll
            for (int mt = 0; mt < 2; mt++) {
                int r = m_base + mt * 16 + (lane >> 2);
                int cc = kk + (lane & 3);
                af[mt][0] = f2tf(As[r * SSTR + cc]);
                af[mt][1] = f2tf(As[(r + 8) * SSTR + cc]);
                af[mt][2] = f2tf(As[r * SSTR + cc + 4]);
                af[mt][3] = f2tf(As[(r + 8) * SSTR + cc + 4]);
            }
            #pragma unroll
            for (int nt = 0; nt < 4; nt++) {
                int n = n_base + nt * 8 + (lane >> 2);
                int cc = kk + (lane & 3);
                bf[nt][0] = f2tf(Bs[n * SSTR + cc]);
                bf[nt][1] = f2tf(Bs[n * SSTR + cc + 4]);
            }
            #pragma unroll
            for (int mt = 0; mt < 2; mt++)
                #pragma unroll
                for (int nt = 0; nt < 4; nt++)
                    mma8(acc[mt][nt], af[mt], bf[nt]);
        }
    }

    // Epilogue: scale by topk weight into per-pair y2
    #pragma unroll
    for (int mt = 0; mt < 2; mt++)
        #pragma unroll
        for (int half = 0; half < 2; half++) {
            int r = m_base + mt * 16 + (lane >> 2) + half * 8;
            int sp = d_sorted[tile * BM + r];
            if (sp < 0) continue;
            float w = tw[sp];
            #pragma unroll
            for (int nt = 0; nt < 4; nt++) {
                int cc = n_base + nt * 8 + (lane & 3) * 2;
                float v0 = w * acc[mt][nt][half * 2 + 0];
                float v1 = w * acc[mt][nt][half * 2 + 1];
                *(float2*)&d_y2[(size_t)sp * HDIM + h0 + cc] = make_float2(v0, v1);
            }
        }
}

// ---------------------------------------------------------------------------
// Reduce: out[t] = y2[2t] + y2[2t+1]
// ---------------------------------------------------------------------------
__global__ void reduce_kernel(float* __restrict__ out) {
    int i = blockIdx.x * blockDim.x + threadIdx.x;
    int t = i >> 8, c4 = i & 255;
    const float4* y = (const float4*)d_y2;
    float4 a = y[(size_t)(t * 2) * 256 + c4];
    float4 b = y[(size_t)(t * 2 + 1) * 256 + c4];
    ((float4*)out)[i] = make_float4(a.x + b.x, a.y + b.y, a.z + b.z, a.w + b.w);
}

// ---------------------------------------------------------------------------
extern "C" void kernel_launch(void* const* d_in, const int* in_sizes, int n_in,
                              void* d_out, int out_size) {
    const float* hs  = (const float*)d_in[0];
    const float* tw  = (const float*)d_in[1];
    const int*   ids = (const int*)d_in[2];
    const float* gw  = (const float*)d_in[3];
    const float* dw  = (const float*)d_in[4];

    cudaFuncSetAttribute(gemm1_kernel, cudaFuncAttributeMaxDynamicSharedMemorySize, SMEM1_BYTES);
    cudaFuncSetAttribute(gemm2_kernel, cudaFuncAttributeMaxDynamicSharedMemorySize, SMEM2_BYTES);

    route_kernel<<<1, 256>>>(ids);
    gemm1_kernel<<<dim3(MAX_TILES, FDIM / BN), 256, SMEM1_BYTES>>>(hs, gw);
    gemm2_kernel<<<dim3(MAX_TILES, HDIM / BN), 256, SMEM2_BYTES>>>(dw, tw);
    reduce_kernel<<<(T_TOK * HDIM / 4) / 256, 256>>>((float*)d_out);
}

// round 4
// speedup vs baseline: 1.2426x; 1.0566x over previous
#include <cuda_runtime.h>
#include <cuda_bf16.h>
#include <cstdint>

// Problem constants
#define T_TOK 2048
#define HDIM  1024
#define FDIM  1024
#define NEXP  8
#define TOPK  2
#define NPAIR (T_TOK * TOPK)

// Tiling
#define BM 128
#define BN 64
#define BK 32
#define NCH (HDIM / BK)          // 32 chunks (HDIM == FDIM)
#define STAGES 3
#define MAX_TILES 40
#define PAD_ROWS (MAX_TILES * BM)

// Swizzled smem: row stride = 32 floats (128B), 16B-block XOR swizzle.
#define A_FLOATS  (BM * BK)              // 4096
#define B_FLOATS  (BN * BK)              // 2048
#define STG1_FLOATS (A_FLOATS + 2 * B_FLOATS)   // 8192 floats = 32KB
#define STG2_FLOATS (A_FLOATS + B_FLOATS)       // 6144 floats = 24KB
#define SMEM1_BYTES (STAGES * STG1_FLOATS * 4)  // 98304
#define SMEM2_BYTES (STAGES * STG2_FLOATS * 4)  // 73728

// Scratch (no allocations allowed)
__device__ int   d_sorted[PAD_ROWS];
__device__ int   d_tile_expert[MAX_TILES];
__device__ int   d_ntiles;
__device__ float d_act[(size_t)PAD_ROWS * FDIM];   // 20 MB
__device__ float d_y2[(size_t)NPAIR * HDIM];       // 16 MB

// ---------------------------------------------------------------------------
// Helpers
// ---------------------------------------------------------------------------
__device__ __forceinline__ uint32_t smem_u32(const void* p) {
    uint32_t a;
    asm("{ .reg .u64 t; cvta.to.shared.u64 t, %1; cvt.u32.u64 %0, t; }" : "=r"(a) : "l"(p));
    return a;
}
__device__ __forceinline__ void cpa16(uint32_t dst, const void* src) {
    asm volatile("cp.async.cg.shared.global [%0], [%1], 16;" :: "r"(dst), "l"(src));
}
__device__ __forceinline__ void cpa16z(uint32_t dst, const void* src, int sz) {
    asm volatile("cp.async.cg.shared.global [%0], [%1], 16, %2;"
                 :: "r"(dst), "l"(src), "r"(sz));
}
#define CPA_COMMIT() asm volatile("cp.async.commit_group;" ::: "memory")
#define CPA_WAIT2()  asm volatile("cp.async.wait_group 2;" ::: "memory")

__device__ __forceinline__ uint32_t f2tf(float x) {
    uint32_t r;
    asm("cvt.rna.tf32.f32 %0, %1;" : "=r"(r) : "f"(x));
    return r;
}
__device__ __forceinline__ void mma8(float* d, const uint32_t* a, const uint32_t* b) {
    asm volatile(
        "mma.sync.aligned.m16n8k8.row.col.f32.tf32.tf32.f32 "
        "{%0,%1,%2,%3}, {%4,%5,%6,%7}, {%8,%9}, {%0,%1,%2,%3};"
        : "+f"(d[0]), "+f"(d[1]), "+f"(d[2]), "+f"(d[3])
        : "r"(a[0]), "r"(a[1]), "r"(a[2]), "r"(a[3]), "r"(b[0]), "r"(b[1]));
}

// Swizzled offset (in floats) for logical (row, col), row stride 32 floats.
// 16B block index = (col>>2) ^ (row & 7).
__device__ __forceinline__ int swoff(int row, int col) {
    return (row << 5) + ((((col >> 2) ^ (row & 7)) << 2) | (col & 3));
}
__device__ __forceinline__ float ldsw(const float* b, int row, int col) {
    return b[swoff(row, col)];
}

// ---------------------------------------------------------------------------
// Routing: group pairs by expert into BM-aligned segments
// ---------------------------------------------------------------------------
__global__ void route_kernel(const int* __restrict__ ids) {
    __shared__ int s_cnt[NEXP], s_start[NEXP], s_cur[NEXP];
    int tid = threadIdx.x;
    if (tid < NEXP) s_cnt[tid] = 0;
    __syncthreads();
    for (int p = tid; p < NPAIR; p += blockDim.x) atomicAdd(&s_cnt[ids[p]], 1);
    __syncthreads();
    if (tid == 0) {
        int acc = 0, nt = 0;
        for (int e = 0; e < NEXP; e++) {
            s_start[e] = acc;
            int te = (s_cnt[e] + BM - 1) / BM;
            for (int i = 0; i < te; i++) d_tile_expert[nt + i] = e;
            nt += te;
            acc += te * BM;
        }
        d_ntiles = nt;
    }
    __syncthreads();
    for (int i = tid; i < PAD_ROWS; i += blockDim.x) d_sorted[i] = -1;
    if (tid < NEXP) s_cur[tid] = s_start[tid];
    __syncthreads();
    for (int p = tid; p < NPAIR; p += blockDim.x) {
        int pos = atomicAdd(&s_cur[ids[p]], 1);
        d_sorted[pos] = p;
    }
}

// ---------------------------------------------------------------------------
// GEMM1: act = silu(x @ Wg^T) * (x @ Wu^T). Grid (MAX_TILES, 16), 256 thr.
// ---------------------------------------------------------------------------
__global__ __launch_bounds__(256, 2)
void gemm1_kernel(const float* __restrict__ hs, const float* __restrict__ gw) {
    int tile = blockIdx.x;
    if (tile >= d_ntiles) return;
    int e  = d_tile_expert[tile];
    int f0 = blockIdx.y * BN;

    extern __shared__ __align__(16) float smem[];
    __shared__ int s_tok[BM];

    int tid = threadIdx.x, lane = tid & 31, warp = tid >> 5;
    if (tid < BM) {
        int sp = d_sorted[tile * BM + tid];
        s_tok[tid] = (sp >= 0) ? (sp >> 1) : -1;
    }
    __syncthreads();

    const float* gwe = gw + (size_t)e * (2 * FDIM) * HDIM;
    uint32_t sbase = smem_u32(smem);

    // Per-thread load slots: A = 1024 float4 (4/thread), Bg/Bu = 512 (2/thread)
    int a_row[4], a_c4[4], a_sz[4];
    const float* a_src[4];
    #pragma unroll
    for (int i = 0; i < 4; i++) {
        int idx = tid + i * 256;
        a_row[i] = idx >> 3; a_c4[i] = idx & 7;
        int tok = s_tok[a_row[i]];
        a_src[i] = (tok >= 0) ? (hs + (size_t)tok * HDIM + a_c4[i] * 4) : hs;
        a_sz[i] = (tok >= 0) ? 16 : 0;
    }

    auto issue = [&](int c) {
        int stg = (c % STAGES) * STG1_FLOATS;
        int k0 = c * BK;
        uint32_t abase = sbase + stg * 4;
        #pragma unroll
        for (int i = 0; i < 4; i++)
            cpa16z(abase + swoff(a_row[i], a_c4[i] * 4) * 4,
                   a_src[i] + (a_sz[i] ? k0 : 0), a_sz[i]);
        uint32_t bgbase = abase + A_FLOATS * 4;
        uint32_t bubase = bgbase + B_FLOATS * 4;
        #pragma unroll
        for (int i = 0; i < 2; i++) {
            int idx = tid + i * 256;
            int row = idx >> 3, c4 = idx & 7;
            cpa16(bgbase + swoff(row, c4 * 4) * 4,
                  gwe + (size_t)(f0 + row) * HDIM + k0 + c4 * 4);
            cpa16(bubase + swoff(row, c4 * 4) * 4,
                  gwe + (size_t)(FDIM + f0 + row) * HDIM + k0 + c4 * 4);
        }
    };

    int wm = warp & 3, wn = warp >> 2;
    int m_base = wm * 32, n_base = wn * 32;

    float accG[2][4][4], accU[2][4][4];
    #pragma unroll
    for (int mt = 0; mt < 2; mt++)
        #pragma unroll
        for (int nt = 0; nt < 4; nt++)
            #pragma unroll
            for (int i = 0; i < 4; i++) { accG[mt][nt][i] = 0.f; accU[mt][nt][i] = 0.f; }

    issue(0); CPA_COMMIT();
    issue(1); CPA_COMMIT();
    issue(2); CPA_COMMIT();

    for (int c = 0; c < NCH; c++) {
        CPA_WAIT2();
        __syncthreads();

        const float* As = smem + (c % STAGES) * STG1_FLOATS;
        const float* Bg = As + A_FLOATS;
        const float* Bu = Bg + B_FLOATS;

        #pragma unroll
        for (int ks = 0; ks < 4; ks++) {
            int kk = ks * 8;
            uint32_t af[2][4], bgf[4][2], buf_[4][2];
            #pragma unroll
            for (int mt = 0; mt < 2; mt++) {
                int r = m_base + mt * 16 + (lane >> 2);
                int cc = kk + (lane & 3);
                af[mt][0] = f2tf(ldsw(As, r, cc));
                af[mt][1] = f2tf(ldsw(As, r + 8, cc));
                af[mt][2] = f2tf(ldsw(As, r, cc + 4));
                af[mt][3] = f2tf(ldsw(As, r + 8, cc + 4));
            }
            #pragma unroll
            for (int nt = 0; nt < 4; nt++) {
                int n = n_base + nt * 8 + (lane >> 2);
                int cc = kk + (lane & 3);
                bgf[nt][0]  = f2tf(ldsw(Bg, n, cc));
                bgf[nt][1]  = f2tf(ldsw(Bg, n, cc + 4));
                buf_[nt][0] = f2tf(ldsw(Bu, n, cc));
                buf_[nt][1] = f2tf(ldsw(Bu, n, cc + 4));
            }
            #pragma unroll
            for (int mt = 0; mt < 2; mt++)
                #pragma unroll
                for (int nt = 0; nt < 4; nt++) {
                    mma8(accG[mt][nt], af[mt], bgf[nt]);
                    mma8(accU[mt][nt], af[mt], buf_[nt]);
                }
        }
        __syncthreads();
        if (c + 3 < NCH) issue(c + 3);
        CPA_COMMIT();
    }

    // Epilogue: silu(g)*u -> act scratch
    #pragma unroll
    for (int mt = 0; mt < 2; mt++)
        #pragma unroll
        for (int nt = 0; nt < 4; nt++)
            #pragma unroll
            for (int half = 0; half < 2; half++) {
                int r = m_base + mt * 16 + (lane >> 2) + half * 8;
                int cc = n_base + nt * 8 + (lane & 3) * 2;
                float g0 = accG[mt][nt][half * 2 + 0];
                float g1 = accG[mt][nt][half * 2 + 1];
                float u0 = accU[mt][nt][half * 2 + 0];
                float u1 = accU[mt][nt][half * 2 + 1];
                float a0 = g0 / (1.f + __expf(-g0)) * u0;
                float a1 = g1 / (1.f + __expf(-g1)) * u1;
                *(float2*)&d_act[(size_t)(tile * BM + r) * FDIM + f0 + cc] =
                    make_float2(a0, a1);
            }
}

// ---------------------------------------------------------------------------
// GEMM2: y2[pair] = tw[pair] * (act @ Wd[e]^T). Grid (MAX_TILES, 16), 256 thr.
// ---------------------------------------------------------------------------
__global__ __launch_bounds__(256, 2)
void gemm2_kernel(const float* __restrict__ dw, const float* __restrict__ tw) {
    int tile = blockIdx.x;
    if (tile >= d_ntiles) return;
    int e  = d_tile_expert[tile];
    int h0 = blockIdx.y * BN;

    extern __shared__ __align__(16) float smem[];

    int tid = threadIdx.x, lane = tid & 31, warp = tid >> 5;
    const float* dwe = dw + (size_t)e * HDIM * FDIM;
    const float* arow = d_act + (size_t)tile * BM * FDIM;
    uint32_t sbase = smem_u32(smem);

    auto issue = [&](int c) {
        int stg = (c % STAGES) * STG2_FLOATS;
        int k0 = c * BK;
        uint32_t abase = sbase + stg * 4;
        #pragma unroll
        for (int i = 0; i < 4; i++) {
            int idx = tid + i * 256;
            int row = idx >> 3, c4 = idx & 7;
            cpa16(abase + swoff(row, c4 * 4) * 4,
                  arow + (size_t)row * FDIM + k0 + c4 * 4);
        }
        uint32_t bbase = abase + A_FLOATS * 4;
        #pragma unroll
        for (int i = 0; i < 2; i++) {
            int idx = tid + i * 256;
            int row = idx >> 3, c4 = idx & 7;
            cpa16(bbase + swoff(row, c4 * 4) * 4,
                  dwe + (size_t)(h0 + row) * FDIM + k0 + c4 * 4);
        }
    };

    int wm = warp & 3, wn = warp >> 2;
    int m_base = wm * 32, n_base = wn * 32;

    float acc[2][4][4];
    #pragma unroll
    for (int mt = 0; mt < 2; mt++)
        #pragma unroll
        for (int nt = 0; nt < 4; nt++)
            #pragma unroll
            for (int i = 0; i < 4; i++) acc[mt][nt][i] = 0.f;

    issue(0); CPA_COMMIT();
    issue(1); CPA_COMMIT();
    issue(2); CPA_COMMIT();

    for (int c = 0; c < NCH; c++) {
        CPA_WAIT2();
        __syncthreads();

        const float* As = smem + (c % STAGES) * STG2_FLOATS;
        const float* Bs = As + A_FLOATS;

        #pragma unroll
        for (int ks = 0; ks < 4; ks++) {
            int kk = ks * 8;
            uint32_t af[2][4], bf[4][2];
            #pragma unroll
            for (int mt = 0; mt < 2; mt++) {
                int r = m_base + mt * 16 + (lane >> 2);
                int cc = kk + (lane & 3);
                af[mt][0] = f2tf(ldsw(As, r, cc));
                af[mt][1] = f2tf(ldsw(As, r + 8, cc));
                af[mt][2] = f2tf(ldsw(As, r, cc + 4));
                af[mt][3] = f2tf(ldsw(As, r + 8, cc + 4));
            }
            #pragma unroll
            for (int nt = 0; nt < 4; nt++) {
                int n = n_base + nt * 8 + (lane >> 2);
                int cc = kk + (lane & 3);
                bf[nt][0] = f2tf(ldsw(Bs, n, cc));
                bf[nt][1] = f2tf(ldsw(Bs, n, cc + 4));
            }
            #pragma unroll
            for (int mt = 0; mt < 2; mt++)
                #pragma unroll
                for (int nt = 0; nt < 4; nt++)
                    mma8(acc[mt][nt], af[mt], bf[nt]);
        }
        __syncthreads();
        if (c + 3 < NCH) issue(c + 3);
        CPA_COMMIT();
    }

    // Epilogue: scale by topk weight into per-pair y2
    #pragma unroll
    for (int mt = 0; mt < 2; mt++)
        #pragma unroll
        for (int half = 0; half < 2; half++) {
            int r = m_base + mt * 16 + (lane >> 2) + half * 8;
            int sp = d_sorted[tile * BM + r];
            if (sp < 0) continue;
            float w = tw[sp];
            #pragma unroll
            for (int nt = 0; nt < 4; nt++) {
                int cc = n_base + nt * 8 + (lane & 3) * 2;
                float v0 = w * acc[mt][nt][half * 2 + 0];
                float v1 = w * acc[mt][nt][half * 2 + 1];
                *(float2*)&d_y2[(size_t)sp * HDIM + h0 + cc] = make_float2(v0, v1);
            }
        }
}

// ---------------------------------------------------------------------------
// Reduce: out[t] = y2[2t] + y2[2t+1]
// ---------------------------------------------------------------------------
__global__ void reduce_kernel(float* __restrict__ out) {
    int i = blockIdx.x * blockDim.x + threadIdx.x;
    int t = i >> 8, c4 = i & 255;
    const float4* y = (const float4*)d_y2;
    float4 a = y[(size_t)(t * 2) * 256 + c4];
    float4 b = y[(size_t)(t * 2 + 1) * 256 + c4];
    ((float4*)out)[i] = make_float4(a.x + b.x, a.y + b.y, a.z + b.z, a.w + b.w);
}

// ---------------------------------------------------------------------------
extern "C" void kernel_launch(void* const* d_in, const int* in_sizes, int n_in,
                              void* d_out, int out_size) {
    const float* hs  = (const float*)d_in[0];
    const float* tw  = (const float*)d_in[1];
    const int*   ids = (const int*)d_in[2];
    const float* gw  = (const float*)d_in[3];
    const float* dw  = (const float*)d_in[4];

    cudaFuncSetAttribute(gemm1_kernel, cudaFuncAttributeMaxDynamicSharedMemorySize, SMEM1_BYTES);
    cudaFuncSetAttribute(gemm2_kernel, cudaFuncAttributeMaxDynamicSharedMemorySize, SMEM2_BYTES);

    route_kernel<<<1, 256>>>(ids);
    gemm1_kernel<<<dim3(MAX_TILES, FDIM / BN), 256, SMEM1_BYTES>>>(hs, gw);
    gemm2_kernel<<<dim3(MAX_TILES, HDIM / BN), 256, SMEM2_BYTES>>>(dw, tw);
    reduce_kernel<<<(T_TOK * HDIM / 4) / 256, 256>>>((float*)d_out);
}

// round 5
// speedup vs baseline: 2.2557x; 1.8154x over previous
#include <cuda_runtime.h>
#include <cuda_fp16.h>
#include <cstdint>

// Problem constants
#define T_TOK 2048
#define HDIM  1024
#define FDIM  1024
#define NEXP  8
#define TOPK  2
#define NPAIR (T_TOK * TOPK)

// Tiling
#define BM 128
#define BN 64
#define BK 32
#define NCH (HDIM / BK)          // 32 chunks (HDIM == FDIM)
#define MAX_TILES 40
#define PAD_ROWS (MAX_TILES * BM)

// fp16 smem tiles, row stride 80 bytes (40 halfs = 5 x 16B granules, gcd(5,8)=1
// -> ldmatrix conflict-free without XOR swizzle).
#define ROWB 80
#define ASZ (BM * ROWB)          // 10240 B
#define BSZ (BN * ROWB)          // 5120 B
#define STG1 (ASZ + 2 * BSZ)     // 20480 B
#define STG2 (ASZ + BSZ)         // 15360 B
#define SMEM1_BYTES (2 * STG1)   // 40960
#define SMEM2_BYTES (2 * STG2)   // 30720

// Scratch (no allocations allowed)
__device__ int    d_sorted[PAD_ROWS];
__device__ int    d_tile_expert[MAX_TILES];
__device__ int    d_ntiles;
__device__ __half d_hs16[(size_t)T_TOK * HDIM];     // 4 MB
__device__ __half d_act[(size_t)PAD_ROWS * FDIM];   // 10 MB
__device__ float  d_y2[(size_t)NPAIR * HDIM];       // 16 MB

// ---------------------------------------------------------------------------
// Helpers
// ---------------------------------------------------------------------------
__device__ __forceinline__ uint32_t smem_u32(const void* p) {
    uint32_t a;
    asm("{ .reg .u64 t; cvta.to.shared.u64 t, %1; cvt.u32.u64 %0, t; }" : "=r"(a) : "l"(p));
    return a;
}
__device__ __forceinline__ uint32_t f2h2(float lo, float hi) {
    __half2 h = __floats2half2_rn(lo, hi);
    return *(uint32_t*)&h;
}
__device__ __forceinline__ void ldsm4(uint32_t* r, uint32_t addr) {
    asm volatile("ldmatrix.sync.aligned.m8n8.x4.shared.b16 {%0,%1,%2,%3}, [%4];"
                 : "=r"(r[0]), "=r"(r[1]), "=r"(r[2]), "=r"(r[3]) : "r"(addr));
}
__device__ __forceinline__ void mma16(float* d, const uint32_t* a, const uint32_t* b) {
    asm volatile(
        "mma.sync.aligned.m16n8k16.row.col.f32.f16.f16.f32 "
        "{%0,%1,%2,%3}, {%4,%5,%6,%7}, {%8,%9}, {%0,%1,%2,%3};"
        : "+f"(d[0]), "+f"(d[1]), "+f"(d[2]), "+f"(d[3])
        : "r"(a[0]), "r"(a[1]), "r"(a[2]), "r"(a[3]), "r"(b[0]), "r"(b[1]));
}

// ---------------------------------------------------------------------------
// hs -> fp16 pre-convert (runs once, 4MB)
// ---------------------------------------------------------------------------
__global__ void hs2h_kernel(const float* __restrict__ hs) {
    int i = blockIdx.x * 256 + threadIdx.x;      // over T*H/8
    const float4* s = (const float4*)hs;
    float4 a = s[i * 2], b = s[i * 2 + 1];
    uint4 o;
    o.x = f2h2(a.x, a.y); o.y = f2h2(a.z, a.w);
    o.z = f2h2(b.x, b.y); o.w = f2h2(b.z, b.w);
    ((uint4*)d_hs16)[i] = o;
}

// ---------------------------------------------------------------------------
// Routing
// ---------------------------------------------------------------------------
__global__ void route_kernel(const int* __restrict__ ids) {
    __shared__ int s_cnt[NEXP], s_start[NEXP], s_cur[NEXP];
    int tid = threadIdx.x;
    if (tid < NEXP) s_cnt[tid] = 0;
    __syncthreads();
    for (int p = tid; p < NPAIR; p += blockDim.x) atomicAdd(&s_cnt[ids[p]], 1);
    __syncthreads();
    if (tid == 0) {
        int acc = 0, nt = 0;
        for (int e = 0; e < NEXP; e++) {
            s_start[e] = acc;
            int te = (s_cnt[e] + BM - 1) / BM;
            for (int i = 0; i < te; i++) d_tile_expert[nt + i] = e;
            nt += te;
            acc += te * BM;
        }
        d_ntiles = nt;
    }
    __syncthreads();
    for (int i = tid; i < PAD_ROWS; i += blockDim.x) d_sorted[i] = -1;
    if (tid < NEXP) s_cur[tid] = s_start[tid];
    __syncthreads();
    for (int p = tid; p < NPAIR; p += blockDim.x) {
        int pos = atomicAdd(&s_cur[ids[p]], 1);
        d_sorted[pos] = p;
    }
}

// ---------------------------------------------------------------------------
// GEMM1: act = silu(x @ Wg^T) * (x @ Wu^T). Grid (MAX_TILES, 16), 256 thr.
// fp16 mma m16n8k16, 2-stage smem, register-pipelined global loads.
// ---------------------------------------------------------------------------
__global__ __launch_bounds__(256, 2)
void gemm1_kernel(const float* __restrict__ gw) {
    int tile = blockIdx.x;
    if (tile >= d_ntiles) return;
    int e  = d_tile_expert[tile];
    int f0 = blockIdx.y * BN;

    extern __shared__ __align__(16) char smem[];
    __shared__ int s_tok[BM];

    int tid = threadIdx.x, lane = tid & 31, warp = tid >> 5;
    if (tid < BM) {
        int sp = d_sorted[tile * BM + tid];
        s_tok[tid] = (sp >= 0) ? (sp >> 1) : 0;   // pad rows read row 0 (discarded)
    }
    __syncthreads();

    const float* gwe = gw + (size_t)e * (2 * FDIM) * HDIM;
    uint32_t sb = smem_u32(smem);

    // A: fp16, 128x32 halfs = 512 16B slots, 2/thread
    int ar[2], ac8[2];
    const __half* asrc[2];
    #pragma unroll
    for (int i = 0; i < 2; i++) {
        int idx = tid + i * 256;
        ar[i] = idx >> 2; ac8[i] = idx & 3;
        asrc[i] = d_hs16 + (size_t)s_tok[ar[i]] * HDIM + ac8[i] * 8;
    }
    // B: fp32, 64x32 floats = 512 float4 slots per matrix, 2/thread each
    int br[2], bc4[2];
    #pragma unroll
    for (int i = 0; i < 2; i++) {
        int idx = tid + i * 256;
        br[i] = idx >> 3; bc4[i] = idx & 7;
    }

    uint4  abuf[2];
    float4 bgbuf[2], bubuf[2];

    auto load = [&](int c) {
        int k0 = c * BK;
        #pragma unroll
        for (int i = 0; i < 2; i++) abuf[i] = *(const uint4*)(asrc[i] + k0);
        #pragma unroll
        for (int i = 0; i < 2; i++) {
            bgbuf[i] = *(const float4*)(gwe + (size_t)(f0 + br[i]) * HDIM + k0 + bc4[i] * 4);
            bubuf[i] = *(const float4*)(gwe + (size_t)(FDIM + f0 + br[i]) * HDIM + k0 + bc4[i] * 4);
        }
    };
    auto sts = [&](int st) {
        uint32_t base = sb + st * STG1;
        #pragma unroll
        for (int i = 0; i < 2; i++)
            *(uint4*)(smem + st * STG1 + ar[i] * ROWB + ac8[i] * 16) = abuf[i];
        (void)base;
        #pragma unroll
        for (int i = 0; i < 2; i++) {
            int off = br[i] * ROWB + bc4[i] * 8;
            *(uint2*)(smem + st * STG1 + ASZ + off) =
                make_uint2(f2h2(bgbuf[i].x, bgbuf[i].y), f2h2(bgbuf[i].z, bgbuf[i].w));
            *(uint2*)(smem + st * STG1 + ASZ + BSZ + off) =
                make_uint2(f2h2(bubuf[i].x, bubuf[i].y), f2h2(bubuf[i].z, bubuf[i].w));
        }
    };

    int wm = warp & 3, wn = warp >> 2;
    int m_base = wm * 32, n_base = wn * 32;

    // ldmatrix lane address components
    int g = lane >> 3;
    int a_row = (g & 1) * 8 + (lane & 7);        // + m_base + mt*16
    int a_kb  = (g >> 1) * 16;                   // + kf*32
    int b_row = (g >> 1) * 8 + (lane & 7);       // + n_base + p*16
    int b_kb  = (g & 1) * 16;                    // + kf*32

    float accG[2][4][4], accU[2][4][4];
    #pragma unroll
    for (int mt = 0; mt < 2; mt++)
        #pragma unroll
        for (int nt = 0; nt < 4; nt++)
            #pragma unroll
            for (int i = 0; i < 4; i++) { accG[mt][nt][i] = 0.f; accU[mt][nt][i] = 0.f; }

    load(0); sts(0); load(1);
    __syncthreads();

    for (int c = 0; c < NCH; c++) {
        int st = c & 1;
        uint32_t Ab  = sb + st * STG1;
        uint32_t Bgb = Ab + ASZ;
        uint32_t Bub = Bgb + BSZ;

        #pragma unroll
        for (int kf = 0; kf < 2; kf++) {
            uint32_t af[2][4], bg[8], bu[8];
            #pragma unroll
            for (int mt = 0; mt < 2; mt++)
                ldsm4(af[mt], Ab + (m_base + mt * 16 + a_row) * ROWB + kf * 32 + a_kb);
            #pragma unroll
            for (int p = 0; p < 2; p++) {
                ldsm4(bg + p * 4, Bgb + (n_base + p * 16 + b_row) * ROWB + kf * 32 + b_kb);
                ldsm4(bu + p * 4, Bub + (n_base + p * 16 + b_row) * ROWB + kf * 32 + b_kb);
            }
            #pragma unroll
            for (int mt = 0; mt < 2; mt++)
                #pragma unroll
                for (int nt = 0; nt < 4; nt++) {
                    mma16(accG[mt][nt], af[mt], bg + nt * 2);
                    mma16(accU[mt][nt], af[mt], bu + nt * 2);
                }
        }
        if (c + 1 < NCH) sts((c + 1) & 1);
        if (c + 2 < NCH) load(c + 2);
        __syncthreads();
    }

    // Epilogue: silu(g)*u -> fp16 act scratch
    #pragma unroll
    for (int mt = 0; mt < 2; mt++)
        #pragma unroll
        for (int nt = 0; nt < 4; nt++)
            #pragma unroll
            for (int half = 0; half < 2; half++) {
                int r  = m_base + mt * 16 + (lane >> 2) + half * 8;
                int cc = n_base + nt * 8 + (lane & 3) * 2;
                float g0 = accG[mt][nt][half * 2 + 0];
                float g1 = accG[mt][nt][half * 2 + 1];
                float u0 = accU[mt][nt][half * 2 + 0];
                float u1 = accU[mt][nt][half * 2 + 1];
                float a0 = g0 / (1.f + __expf(-g0)) * u0;
                float a1 = g1 / (1.f + __expf(-g1)) * u1;
                *(__half2*)&d_act[(size_t)(tile * BM + r) * FDIM + f0 + cc] =
                    __floats2half2_rn(a0, a1);
            }
}

// ---------------------------------------------------------------------------
// GEMM2: y2[pair] = tw[pair] * (act @ Wd[e]^T). Grid (MAX_TILES, 16), 256 thr.
// ---------------------------------------------------------------------------
__global__ __launch_bounds__(256, 2)
void gemm2_kernel(const float* __restrict__ dw, const float* __restrict__ tw) {
    int tile = blockIdx.x;
    if (tile >= d_ntiles) return;
    int e  = d_tile_expert[tile];
    int h0 = blockIdx.y * BN;

    extern __shared__ __align__(16) char smem[];

    int tid = threadIdx.x, lane = tid & 31, warp = tid >> 5;
    const float*  dwe  = dw + (size_t)e * HDIM * FDIM;
    const __half* arow = d_act + (size_t)tile * BM * FDIM;
    uint32_t sb = smem_u32(smem);

    int ar[2], ac8[2], br[2], bc4[2];
    #pragma unroll
    for (int i = 0; i < 2; i++) {
        int idx = tid + i * 256;
        ar[i] = idx >> 2; ac8[i] = idx & 3;
        br[i] = idx >> 3; bc4[i] = idx & 7;
    }

    uint4  abuf[2];
    float4 bbuf[2];

    auto load = [&](int c) {
        int k0 = c * BK;
        #pragma unroll
        for (int i = 0; i < 2; i++)
            abuf[i] = *(const uint4*)(arow + (size_t)ar[i] * FDIM + k0 + ac8[i] * 8);
        #pragma unroll
        for (int i = 0; i < 2; i++)
            bbuf[i] = *(const float4*)(dwe + (size_t)(h0 + br[i]) * FDIM + k0 + bc4[i] * 4);
    };
    auto sts = [&](int st) {
        #pragma unroll
        for (int i = 0; i < 2; i++)
            *(uint4*)(smem + st * STG2 + ar[i] * ROWB + ac8[i] * 16) = abuf[i];
        #pragma unroll
        for (int i = 0; i < 2; i++) {
            int off = br[i] * ROWB + bc4[i] * 8;
            *(uint2*)(smem + st * STG2 + ASZ + off) =
                make_uint2(f2h2(bbuf[i].x, bbuf[i].y), f2h2(bbuf[i].z, bbuf[i].w));
        }
    };

    int wm = warp & 3, wn = warp >> 2;
    int m_base = wm * 32, n_base = wn * 32;

    int g = lane >> 3;
    int a_row = (g & 1) * 8 + (lane & 7);
    int a_kb  = (g >> 1) * 16;
    int b_row = (g >> 1) * 8 + (lane & 7);
    int b_kb  = (g & 1) * 16;

    float acc[2][4][4];
    #pragma unroll
    for (int mt = 0; mt < 2; mt++)
        #pragma unroll
        for (int nt = 0; nt < 4; nt++)
            #pragma unroll
            for (int i = 0; i < 4; i++) acc[mt][nt][i] = 0.f;

    load(0); sts(0); load(1);
    __syncthreads();

    for (int c = 0; c < NCH; c++) {
        int st = c & 1;
        uint32_t Ab = sb + st * STG2;
        uint32_t Bb = Ab + ASZ;

        #pragma unroll
        for (int kf = 0; kf < 2; kf++) {
            uint32_t af[2][4], bf[8];
            #pragma unroll
            for (int mt = 0; mt < 2; mt++)
                ldsm4(af[mt], Ab + (m_base + mt * 16 + a_row) * ROWB + kf * 32 + a_kb);
            #pragma unroll
            for (int p = 0; p < 2; p++)
                ldsm4(bf + p * 4, Bb + (n_base + p * 16 + b_row) * ROWB + kf * 32 + b_kb);
            #pragma unroll
            for (int mt = 0; mt < 2; mt++)
                #pragma unroll
                for (int nt = 0; nt < 4; nt++)
                    mma16(acc[mt][nt], af[mt], bf + nt * 2);
        }
        if (c + 1 < NCH) sts((c + 1) & 1);
        if (c + 2 < NCH) load(c + 2);
        __syncthreads();
    }

    // Epilogue: scale by topk weight into per-pair y2 (fp32)
    #pragma unroll
    for (int mt = 0; mt < 2; mt++)
        #pragma unroll
        for (int half = 0; half < 2; half++) {
            int r  = m_base + mt * 16 + (lane >> 2) + half * 8;
            int sp = d_sorted[tile * BM + r];
            if (sp < 0) continue;
            float w = tw[sp];
            #pragma unroll
            for (int nt = 0; nt < 4; nt++) {
                int cc = n_base + nt * 8 + (lane & 3) * 2;
                float v0 = w * acc[mt][nt][half * 2 + 0];
                float v1 = w * acc[mt][nt][half * 2 + 1];
                *(float2*)&d_y2[(size_t)sp * HDIM + h0 + cc] = make_float2(v0, v1);
            }
        }
}

// ---------------------------------------------------------------------------
// Reduce: out[t] = y2[2t] + y2[2t+1]
// ---------------------------------------------------------------------------
__global__ void reduce_kernel(float* __restrict__ out) {
    int i = blockIdx.x * blockDim.x + threadIdx.x;
    int t = i >> 8, c4 = i & 255;
    const float4* y = (const float4*)d_y2;
    float4 a = y[(size_t)(t * 2) * 256 + c4];
    float4 b = y[(size_t)(t * 2 + 1) * 256 + c4];
    ((float4*)out)[i] = make_float4(a.x + b.x, a.y + b.y, a.z + b.z, a.w + b.w);
}

// ---------------------------------------------------------------------------
extern "C" void kernel_launch(void* const* d_in, const int* in_sizes, int n_in,
                              void* d_out, int out_size) {
    const float* hs  = (const float*)d_in[0];
    const float* tw  = (const float*)d_in[1];
    const int*   ids = (const int*)d_in[2];
    const float* gw  = (const float*)d_in[3];
    const float* dw  = (const float*)d_in[4];

    cudaFuncSetAttribute(gemm1_kernel, cudaFuncAttributeMaxDynamicSharedMemorySize, SMEM1_BYTES);
    cudaFuncSetAttribute(gemm2_kernel, cudaFuncAttributeMaxDynamicSharedMemorySize, SMEM2_BYTES);

    hs2h_kernel<<<T_TOK * HDIM / 8 / 256, 256>>>(hs);
    route_kernel<<<1, 256>>>(ids);
    gemm1_kernel<<<dim3(MAX_TILES, FDIM / BN), 256, SMEM1_BYTES>>>(gw);
    gemm2_kernel<<<dim3(MAX_TILES, HDIM / BN), 256, SMEM2_BYTES>>>(dw, tw);
    reduce_kernel<<<(T_TOK * HDIM / 4) / 256, 256>>>((float*)d_out);
}

// round 6
// speedup vs baseline: 2.4391x; 1.0813x over previous
#include <cuda_runtime.h>
#include <cuda_fp16.h>
#include <cstdint>

// Problem constants
#define T_TOK 2048
#define HDIM  1024
#define FDIM  1024
#define NEXP  8
#define TOPK  2
#define NPAIR (T_TOK * TOPK)

// Tiling
#define BM 128
#define BK 32
#define NCH (HDIM / BK)          // 32 chunks (HDIM == FDIM)
#define MAX_TILES 40
#define PAD_ROWS (MAX_TILES * BM)

// fp16 smem rows, stride 80 B (5 x 16B granules, gcd(5,8)=1 -> ldmatrix
// conflict-free). A: 4-stage cp.async. B: 2-stage reg-pipelined cvt.
#define ROWB 80
#define TILEB (BM * ROWB)        // 10240 B (both A tile and B tile are 128 rows)
#define A_STAGES 4
#define B_STAGES 2
#define SMEM_BYTES (A_STAGES * TILEB + B_STAGES * TILEB)   // 61440

// Scratch (no allocations allowed)
__device__ int    d_sorted[PAD_ROWS];
__device__ int    d_tile_expert[MAX_TILES];
__device__ int    d_ntiles;
__device__ __half d_hs16[(size_t)T_TOK * HDIM];     // 4 MB
__device__ __half d_act[(size_t)PAD_ROWS * FDIM];   // 10 MB
__device__ float  d_y2[(size_t)NPAIR * HDIM];       // 16 MB

// ---------------------------------------------------------------------------
// Helpers
// ---------------------------------------------------------------------------
__device__ __forceinline__ uint32_t smem_u32(const void* p) {
    uint32_t a;
    asm("{ .reg .u64 t; cvta.to.shared.u64 t, %1; cvt.u32.u64 %0, t; }" : "=r"(a) : "l"(p));
    return a;
}
__device__ __forceinline__ uint32_t f2h2(float lo, float hi) {
    __half2 h = __floats2half2_rn(lo, hi);
    return *(uint32_t*)&h;
}
__device__ __forceinline__ void cpa16(uint32_t dst, const void* src) {
    asm volatile("cp.async.cg.shared.global [%0], [%1], 16;" :: "r"(dst), "l"(src));
}
#define CPA_COMMIT() asm volatile("cp.async.commit_group;" ::: "memory")
#define CPA_WAIT2()  asm volatile("cp.async.wait_group 2;" ::: "memory")

__device__ __forceinline__ void ldsm4(uint32_t* r, uint32_t addr) {
    asm volatile("ldmatrix.sync.aligned.m8n8.x4.shared.b16 {%0,%1,%2,%3}, [%4];"
                 : "=r"(r[0]), "=r"(r[1]), "=r"(r[2]), "=r"(r[3]) : "r"(addr));
}
__device__ __forceinline__ void mma16(float* d, const uint32_t* a, const uint32_t* b) {
    asm volatile(
        "mma.sync.aligned.m16n8k16.row.col.f32.f16.f16.f32 "
        "{%0,%1,%2,%3}, {%4,%5,%6,%7}, {%8,%9}, {%0,%1,%2,%3};"
        : "+f"(d[0]), "+f"(d[1]), "+f"(d[2]), "+f"(d[3])
        : "r"(a[0]), "r"(a[1]), "r"(a[2]), "r"(a[3]), "r"(b[0]), "r"(b[1]));
}

// ---------------------------------------------------------------------------
// hs -> fp16 pre-convert
// ---------------------------------------------------------------------------
__global__ void hs2h_kernel(const float* __restrict__ hs) {
    int i = blockIdx.x * 256 + threadIdx.x;
    const float4* s = (const float4*)hs;
    float4 a = s[i * 2], b = s[i * 2 + 1];
    uint4 o;
    o.x = f2h2(a.x, a.y); o.y = f2h2(a.z, a.w);
    o.z = f2h2(b.x, b.y); o.w = f2h2(b.z, b.w);
    ((uint4*)d_hs16)[i] = o;
}

// ---------------------------------------------------------------------------
// Routing
// ---------------------------------------------------------------------------
__global__ void route_kernel(const int* __restrict__ ids) {
    __shared__ int s_cnt[NEXP], s_start[NEXP], s_cur[NEXP];
    int tid = threadIdx.x;
    if (tid < NEXP) s_cnt[tid] = 0;
    __syncthreads();
    for (int p = tid; p < NPAIR; p += blockDim.x) atomicAdd(&s_cnt[ids[p]], 1);
    __syncthreads();
    if (tid == 0) {
        int acc = 0, nt = 0;
        for (int e = 0; e < NEXP; e++) {
            s_start[e] = acc;
            int te = (s_cnt[e] + BM - 1) / BM;
            for (int i = 0; i < te; i++) d_tile_expert[nt + i] = e;
            nt += te;
            acc += te * BM;
        }
        d_ntiles = nt;
    }
    __syncthreads();
    for (int i = tid; i < PAD_ROWS; i += blockDim.x) d_sorted[i] = -1;
    if (tid < NEXP) s_cur[tid] = s_start[tid];
    __syncthreads();
    for (int p = tid; p < NPAIR; p += blockDim.x) {
        int pos = atomicAdd(&s_cur[ids[p]], 1);
        d_sorted[pos] = p;
    }
}

// ---------------------------------------------------------------------------
// GEMM1: act = silu(x @ Wg^T) * (x @ Wu^T).
// 128 thr (4 warps, 2x2), warp tile 64m x 32f DUAL (gate+up). Grid (40,16).
// A (fp16): 4-stage cp.async. B (fp32, 64 gate + 64 up rows): 2-stage regs.
// ---------------------------------------------------------------------------
__global__ __launch_bounds__(128, 2)
void gemm1_kernel(const float* __restrict__ gw) {
    int tile = blockIdx.x;
    if (tile >= d_ntiles) return;
    int e  = d_tile_expert[tile];
    int f0 = blockIdx.y * 64;

    extern __shared__ __align__(16) char smem[];
    __shared__ int s_tok[BM];

    int tid = threadIdx.x, lane = tid & 31, warp = tid >> 5;
    if (tid < BM) {
        int sp = d_sorted[tile * BM + tid];
        s_tok[tid] = (sp >= 0) ? (sp >> 1) : 0;
    }
    __syncthreads();

    const float* gwe = gw + (size_t)e * (2 * FDIM) * HDIM;
    uint32_t sb = smem_u32(smem);
    uint32_t bbase0 = sb + A_STAGES * TILEB;

    // A cp.async slots: 512 x 16B, 4/thread
    int ar[4], ac8[4];
    const __half* asrc[4];
    #pragma unroll
    for (int i = 0; i < 4; i++) {
        int idx = tid + i * 128;
        ar[i] = idx >> 2; ac8[i] = idx & 3;
        asrc[i] = d_hs16 + (size_t)s_tok[ar[i]] * HDIM + ac8[i] * 8;
    }
    auto issueA = [&](int c) {
        uint32_t ab = sb + (c & 3) * TILEB;
        #pragma unroll
        for (int i = 0; i < 4; i++)
            cpa16(ab + ar[i] * ROWB + ac8[i] * 16, asrc[i] + c * BK);
    };

    // B: 128 rows (64 gate + 64 up) x 32 fp32 = 1024 float4, 8/thread
    int br[8], bc4[8];
    const float* bsrc[8];
    #pragma unroll
    for (int i = 0; i < 8; i++) {
        int idx = tid + i * 128;
        br[i] = idx >> 3; bc4[i] = idx & 7;
        int grow = (br[i] < 64) ? (f0 + br[i]) : (FDIM + f0 + (br[i] - 64));
        bsrc[i] = gwe + (size_t)grow * HDIM + bc4[i] * 4;
    }
    float4 bbuf[8];
    auto loadB = [&](int c) {
        #pragma unroll
        for (int i = 0; i < 8; i++) bbuf[i] = *(const float4*)(bsrc[i] + c * BK);
    };
    auto stsB = [&](int c) {
        char* bs = smem + A_STAGES * TILEB + (c & 1) * TILEB;
        #pragma unroll
        for (int i = 0; i < 8; i++)
            *(uint2*)(bs + br[i] * ROWB + bc4[i] * 8) =
                make_uint2(f2h2(bbuf[i].x, bbuf[i].y), f2h2(bbuf[i].z, bbuf[i].w));
    };

    int wm = warp & 1, wn = warp >> 1;
    int m_base = wm * 64, f_base = wn * 32;

    int g = lane >> 3;
    int a_row = (g & 1) * 8 + (lane & 7);
    int a_kb  = (g >> 1) * 16;
    int b_row = (g >> 1) * 8 + (lane & 7);
    int b_kb  = (g & 1) * 16;

    float accG[4][4][4], accU[4][4][4];
    #pragma unroll
    for (int mt = 0; mt < 4; mt++)
        #pragma unroll
        for (int nt = 0; nt < 4; nt++)
            #pragma unroll
            for (int i = 0; i < 4; i++) { accG[mt][nt][i] = 0.f; accU[mt][nt][i] = 0.f; }

    issueA(0); CPA_COMMIT();
    issueA(1); CPA_COMMIT();
    issueA(2); CPA_COMMIT();
    loadB(0); stsB(0); loadB(1);

    for (int c = 0; c < NCH; c++) {
        CPA_WAIT2();
        __syncthreads();

        uint32_t Ab = sb + (c & 3) * TILEB;
        uint32_t Bb = bbase0 + (c & 1) * TILEB;

        #pragma unroll
        for (int kf = 0; kf < 2; kf++) {
            uint32_t af[4][4], bg[8], bu[8];
            #pragma unroll
            for (int mt = 0; mt < 4; mt++)
                ldsm4(af[mt], Ab + (m_base + mt * 16 + a_row) * ROWB + kf * 32 + a_kb);
            #pragma unroll
            for (int p = 0; p < 2; p++) {
                ldsm4(bg + p * 4, Bb + (f_base + p * 16 + b_row) * ROWB + kf * 32 + b_kb);
                ldsm4(bu + p * 4, Bb + (64 + f_base + p * 16 + b_row) * ROWB + kf * 32 + b_kb);
            }
            #pragma unroll
            for (int mt = 0; mt < 4; mt++)
                #pragma unroll
                for (int nt = 0; nt < 4; nt++) {
                    mma16(accG[mt][nt], af[mt], bg + nt * 2);
                    mma16(accU[mt][nt], af[mt], bu + nt * 2);
                }
        }
        if (c + 1 < NCH) stsB(c + 1);
        if (c + 2 < NCH) loadB(c + 2);
        if (c + 3 < NCH) issueA(c + 3);
        CPA_COMMIT();
    }

    // Epilogue: silu(g)*u -> fp16 act scratch
    #pragma unroll
    for (int mt = 0; mt < 4; mt++)
        #pragma unroll
        for (int nt = 0; nt < 4; nt++)
            #pragma unroll
            for (int half = 0; half < 2; half++) {
                int r  = m_base + mt * 16 + (lane >> 2) + half * 8;
                int cc = f0 + f_base + nt * 8 + (lane & 3) * 2;
                float g0 = accG[mt][nt][half * 2 + 0];
                float g1 = accG[mt][nt][half * 2 + 1];
                float u0 = accU[mt][nt][half * 2 + 0];
                float u1 = accU[mt][nt][half * 2 + 1];
                float a0 = g0 / (1.f + __expf(-g0)) * u0;
                float a1 = g1 / (1.f + __expf(-g1)) * u1;
                *(__half2*)&d_act[(size_t)(tile * BM + r) * FDIM + cc] =
                    __floats2half2_rn(a0, a1);
            }
}

// ---------------------------------------------------------------------------
// GEMM2: y2[pair] = tw[pair] * (act @ Wd[e]^T).
// 128 thr (4 warps, 2x2), warp tile 64x64. BN=128. Grid (40,8).
// ---------------------------------------------------------------------------
__global__ __launch_bounds__(128, 2)
void gemm2_kernel(const float* __restrict__ dw, const float* __restrict__ tw) {
    int tile = blockIdx.x;
    if (tile >= d_ntiles) return;
    int e  = d_tile_expert[tile];
    int h0 = blockIdx.y * 128;

    extern __shared__ __align__(16) char smem[];

    int tid = threadIdx.x, lane = tid & 31, warp = tid >> 5;
    const float*  dwe  = dw + (size_t)e * HDIM * FDIM;
    const __half* arow = d_act + (size_t)tile * BM * FDIM;
    uint32_t sb = smem_u32(smem);
    uint32_t bbase0 = sb + A_STAGES * TILEB;

    // A cp.async slots: 512 x 16B, 4/thread
    int ar[4], ac8[4];
    #pragma unroll
    for (int i = 0; i < 4; i++) {
        int idx = tid + i * 128;
        ar[i] = idx >> 2; ac8[i] = idx & 3;
    }
    auto issueA = [&](int c) {
        uint32_t ab = sb + (c & 3) * TILEB;
        #pragma unroll
        for (int i = 0; i < 4; i++)
            cpa16(ab + ar[i] * ROWB + ac8[i] * 16,
                  arow + (size_t)ar[i] * FDIM + c * BK + ac8[i] * 8);
    };

    // B: 128 rows x 32 fp32 = 1024 float4, 8/thread
    int br[8], bc4[8];
    #pragma unroll
    for (int i = 0; i < 8; i++) {
        int idx = tid + i * 128;
        br[i] = idx >> 3; bc4[i] = idx & 7;
    }
    float4 bbuf[8];
    auto loadB = [&](int c) {
        #pragma unroll
        for (int i = 0; i < 8; i++)
            bbuf[i] = *(const float4*)(dwe + (size_t)(h0 + br[i]) * FDIM + c * BK + bc4[i] * 4);
    };
    auto stsB = [&](int c) {
        char* bs = smem + A_STAGES * TILEB + (c & 1) * TILEB;
        #pragma unroll
        for (int i = 0; i < 8; i++)
            *(uint2*)(bs + br[i] * ROWB + bc4[i] * 8) =
                make_uint2(f2h2(bbuf[i].x, bbuf[i].y), f2h2(bbuf[i].z, bbuf[i].w));
    };

    int wm = warp & 1, wn = warp >> 1;
    int m_base = wm * 64, n_base = wn * 64;

    int g = lane >> 3;
    int a_row = (g & 1) * 8 + (lane & 7);
    int a_kb  = (g >> 1) * 16;
    int b_row = (g >> 1) * 8 + (lane & 7);
    int b_kb  = (g & 1) * 16;

    float acc[4][8][4];
    #pragma unroll
    for (int mt = 0; mt < 4; mt++)
        #pragma unroll
        for (int nt = 0; nt < 8; nt++)
            #pragma unroll
            for (int i = 0; i < 4; i++) acc[mt][nt][i] = 0.f;

    issueA(0); CPA_COMMIT();
    issueA(1); CPA_COMMIT();
    issueA(2); CPA_COMMIT();
    loadB(0); stsB(0); loadB(1);

    for (int c = 0; c < NCH; c++) {
        CPA_WAIT2();
        __syncthreads();

        uint32_t Ab = sb + (c & 3) * TILEB;
        uint32_t Bb = bbase0 + (c & 1) * TILEB;

        #pragma unroll
        for (int kf = 0; kf < 2; kf++) {
            uint32_t af[4][4], bf[16];
            #pragma unroll
            for (int mt = 0; mt < 4; mt++)
                ldsm4(af[mt], Ab + (m_base + mt * 16 + a_row) * ROWB + kf * 32 + a_kb);
            #pragma unroll
            for (int p = 0; p < 4; p++)
                ldsm4(bf + p * 4, Bb + (n_base + p * 16 + b_row) * ROWB + kf * 32 + b_kb);
            #pragma unroll
            for (int mt = 0; mt < 4; mt++)
                #pragma unroll
                for (int nt = 0; nt < 8; nt++)
                    mma16(acc[mt][nt], af[mt], bf + nt * 2);
        }
        if (c + 1 < NCH) stsB(c + 1);
        if (c + 2 < NCH) loadB(c + 2);
        if (c + 3 < NCH) issueA(c + 3);
        CPA_COMMIT();
    }

    // Epilogue: scale by topk weight into per-pair y2 (fp32)
    #pragma unroll
    for (int mt = 0; mt < 4; mt++)
        #pragma unroll
        for (int half = 0; half < 2; half++) {
            int r  = m_base + mt * 16 + (lane >> 2) + half * 8;
            int sp = d_sorted[tile * BM + r];
            if (sp < 0) continue;
            float w = tw[sp];
            #pragma unroll
            for (int nt = 0; nt < 8; nt++) {
                int cc = h0 + n_base + nt * 8 + (lane & 3) * 2;
                float v0 = w * acc[mt][nt][half * 2 + 0];
                float v1 = w * acc[mt][nt][half * 2 + 1];
                *(float2*)&d_y2[(size_t)sp * HDIM + cc] = make_float2(v0, v1);
            }
        }
}

// ---------------------------------------------------------------------------
// Reduce: out[t] = y2[2t] + y2[2t+1]
// ---------------------------------------------------------------------------
__global__ void reduce_kernel(float* __restrict__ out) {
    int i = blockIdx.x * blockDim.x + threadIdx.x;
    int t = i >> 8, c4 = i & 255;
    const float4* y = (const float4*)d_y2;
    float4 a = y[(size_t)(t * 2) * 256 + c4];
    float4 b = y[(size_t)(t * 2 + 1) * 256 + c4];
    ((float4*)out)[i] = make_float4(a.x + b.x, a.y + b.y, a.z + b.z, a.w + b.w);
}

// ---------------------------------------------------------------------------
extern "C" void kernel_launch(void* const* d_in, const int* in_sizes, int n_in,
                              void* d_out, int out_size) {
    const float* hs  = (const float*)d_in[0];
    const float* tw  = (const float*)d_in[1];
    const int*   ids = (const int*)d_in[2];
    const float* gw  = (const float*)d_in[3];
    const float* dw  = (const float*)d_in[4];

    cudaFuncSetAttribute(gemm1_kernel, cudaFuncAttributeMaxDynamicSharedMemorySize, SMEM_BYTES);
    cudaFuncSetAttribute(gemm2_kernel, cudaFuncAttributeMaxDynamicSharedMemorySize, SMEM_BYTES);

    hs2h_kernel<<<T_TOK * HDIM / 8 / 256, 256>>>(hs);
    route_kernel<<<1, 256>>>(ids);
    gemm1_kernel<<<dim3(MAX_TILES, FDIM / 64), 128, SMEM_BYTES>>>(gw);
    gemm2_kernel<<<dim3(MAX_TILES, HDIM / 128), 128, SMEM_BYTES>>>(dw, tw);
    reduce_kernel<<<(T_TOK * HDIM / 4) / 256, 256>>>((float*)d_out);
}